// round 4
// baseline (speedup 1.0000x reference)
#include <cuda_runtime.h>
#include <cstdint>

// Problem constants
#define BB    8
#define C     128
#define W     256
#define H     256
#define NPIX  (W*H)          // 65536 pixels per image

// Output buffer layout (concatenated f32, raw reshapes):
#define OFF_CENTERS 0
#define OFF_LABELS  256
#define OFF_ONEHOT  (OFF_LABELS + BB*NPIX)
#define OFF_DIST    (OFF_ONEHOT + BB*2*NPIX)
#define OFF_LABELT  (OFF_DIST   + BB*2*NPIX)

// Scratch (__device__ globals). All overwrite-slot semantics -> no zero-init.
// g_mask: batch-7 labels as bits. For float4 index j (0..16383):
//   word = g_mask[j>>5], lane = j&31, label(pixel 4j+c) = bit lane of comp c.
__device__ uint4 g_mask[512];
// g_part[(k*128+ch)*8 + tile]: per-tile per-channel label-k sums (batch 7)
__device__ float g_part[256 * 8];
__device__ int   g_arrive = 0;   // center-block arrival counter; last resets

// ---------------------------------------------------------------------------
// Shared per-pixel-tile worker: dot vs both centers, labels, big outputs.
// ---------------------------------------------------------------------------
template <bool STREAM>
__device__ __forceinline__ void main_tile(const float* __restrict__ F,
                                          const float* __restrict__ sc,
                                          float* __restrict__ out,
                                          int b, int p4) {
    int n0 = p4 << 2;
    const float4* Fb = reinterpret_cast<const float4*>(F + (size_t)b * C * NPIX);

    float4 a0 = make_float4(0.f,0.f,0.f,0.f);
    float4 a1 = make_float4(0.f,0.f,0.f,0.f);
    #pragma unroll 8
    for (int ch = 0; ch < C; ch++) {
        float4 f = STREAM ? __ldcs(&Fb[ch * (NPIX/4) + p4])
                          : Fb[ch * (NPIX/4) + p4];
        float c0 = sc[ch];
        float c1 = sc[C + ch];
        a0.x += f.x*c0; a0.y += f.y*c0; a0.z += f.z*c0; a0.w += f.w*c0;
        a1.x += f.x*c1; a1.y += f.y*c1; a1.z += f.z*c1; a1.w += f.w*c1;
    }

    float d0x = 0.5f - 0.5f*a0.x, d1x = 0.5f - 0.5f*a1.x;
    float d0y = 0.5f - 0.5f*a0.y, d1y = 0.5f - 0.5f*a1.y;
    float d0z = 0.5f - 0.5f*a0.z, d1z = 0.5f - 0.5f*a1.z;
    float d0w = 0.5f - 0.5f*a0.w, d1w = 0.5f - 0.5f*a1.w;

    int lx = d1x < d0x, ly = d1y < d0y, lz = d1z < d0z, lw = d1w < d0w;
    float4 lab = make_float4((float)lx, (float)ly, (float)lz, (float)lw);

    __stcs(reinterpret_cast<float4*>(out + OFF_LABELS + (size_t)b*NPIX + n0), lab);
    __stcs(reinterpret_cast<float4*>(out + OFF_LABELT + (size_t)b*NPIX + n0), lab);

    float4* outO = reinterpret_cast<float4*>(out + OFF_ONEHOT + (size_t)b*2*NPIX + 2*n0);
    __stcs(outO + 0, make_float4(1.f - lab.x, lab.x, 1.f - lab.y, lab.y));
    __stcs(outO + 1, make_float4(1.f - lab.z, lab.z, 1.f - lab.w, lab.w));

    float4* outD = reinterpret_cast<float4*>(out + OFF_DIST + (size_t)b*2*NPIX + 2*n0);
    __stcs(outD + 0, make_float4(d0x, d1x, d0y, d1y));
    __stcs(outD + 1, make_float4(d0z, d1z, d0w, d1w));

    if (!STREAM) {   // batch 7: publish labels as ballot bitmask
        unsigned bx = __ballot_sync(0xffffffffu, lx);
        unsigned by = __ballot_sync(0xffffffffu, ly);
        unsigned bz = __ballot_sync(0xffffffffu, lz);
        unsigned bw = __ballot_sync(0xffffffffu, lw);
        if ((p4 & 31) == 0) g_mask[p4 >> 5] = make_uint4(bx, by, bz, bw);
    }
}

// ---------------------------------------------------------------------------
// Kernel A: batch 7 only. 128 blocks x 128 threads (1 float4/thread) so
// ~128 SMs stream the 32MB concurrently; normal loads leave F7 hot in L2.
// ---------------------------------------------------------------------------
__global__ void __launch_bounds__(128) k_b7(const float* __restrict__ F,
                                            const float* __restrict__ Cinit,
                                            float* __restrict__ out) {
    __shared__ float sc[2*C];
    int t = threadIdx.x;
    sc[t] = Cinit[t];
    sc[t + 128] = Cinit[t + 128];
    __syncthreads();

    int p4 = blockIdx.x * 128 + t;     // 0..16383
    main_tile<false>(F, sc, out, BB - 1, p4);
}

// ---------------------------------------------------------------------------
// Kernel B: 448 main blocks (b=0..6, streaming) + 1024 center blocks.
// Main blocks are issued first (long, DRAM-bound); center blocks fill the
// remaining occupancy and read F7 from the L2 kernel A just warmed, fully
// overlapped with the DRAM stream. Last-arriving center block does epilogue.
// ---------------------------------------------------------------------------
__global__ void __launch_bounds__(256) k_rest(const float* __restrict__ F,
                                              const float* __restrict__ Cinit,
                                              float* __restrict__ out) {
    int t   = threadIdx.x;
    int blk = blockIdx.x;

    if (blk < 448) {
        // ---------------- main pass, batches 0..6 ----------------
        __shared__ float sc[2*C];
        sc[t] = Cinit[t];
        __syncthreads();
        int b    = blk >> 6;
        int slot = blk & 63;
        main_tile<true>(F, sc, out, b, slot * 256 + t);
        return;
    }

    // ---------------- center pass, batch 7 channel sums ----------------
    __shared__ float wa[8], w1[8];
    __shared__ int   wc[8];
    __shared__ int   s_done, s_cnt;

    int cidx = blk - 448;           // 0..1023
    int ch   = cidx >> 3;           // 0..127
    int tile = cidx & 7;            // 0..7
    int wid  = t >> 5, lane = t & 31;

    const float4* Fp = reinterpret_cast<const float4*>(
        F + ((size_t)(BB-1) * C + ch) * NPIX);
    int base = tile * 2048;         // float4 base (8192 pixels per tile)

    float sa = 0.f, s1 = 0.f;
    #pragma unroll
    for (int i = 0; i < 8; i++) {
        int j = base + i*256 + t;           // j&31 == lane
        float4 f = Fp[j];
        uint4  m = g_mask[j >> 5];
        float mx = (float)((m.x >> lane) & 1u);
        float my = (float)((m.y >> lane) & 1u);
        float mz = (float)((m.z >> lane) & 1u);
        float mw = (float)((m.w >> lane) & 1u);
        sa += f.x + f.y + f.z + f.w;
        s1 += f.x*mx + f.y*my + f.z*mz + f.w*mw;
    }

    #pragma unroll
    for (int o = 16; o > 0; o >>= 1) {
        sa += __shfl_down_sync(0xffffffffu, sa, o);
        s1 += __shfl_down_sync(0xffffffffu, s1, o);
    }
    if (lane == 0) { wa[wid] = sa; w1[wid] = s1; }
    __syncthreads();
    if (t == 0) {
        float va = 0.f, v1 = 0.f;
        #pragma unroll
        for (int i = 0; i < 8; i++) { va += wa[i]; v1 += w1[i]; }
        g_part[(ch)     * 8 + tile] = va - v1;   // label 0 sum
        g_part[(C + ch) * 8 + tile] = v1;        // label 1 sum
    }

    // ---- arrival; last center block does the epilogue ----
    __syncthreads();
    if (t == 0) {
        __threadfence();
        int old = atomicAdd(&g_arrive, 1);
        s_done = (old == 1024 - 1);
    }
    __syncthreads();
    if (!s_done) return;
    __threadfence();

    // label-1 count via mask popcount (512 uint4 / 256 threads = 2 each)
    {
        uint4 m0 = g_mask[2*t], m1 = g_mask[2*t + 1];
        int c = __popc(m0.x) + __popc(m0.y) + __popc(m0.z) + __popc(m0.w)
              + __popc(m1.x) + __popc(m1.y) + __popc(m1.z) + __popc(m1.w);
        #pragma unroll
        for (int o = 16; o > 0; o >>= 1)
            c += __shfl_down_sync(0xffffffffu, c, o);
        if (lane == 0) wc[wid] = c;
        __syncthreads();
        if (t == 0) {
            int v = 0;
            #pragma unroll
            for (int i = 0; i < 8; i++) v += wc[i];
            s_cnt = v;
        }
        __syncthreads();
    }

    // reduce the 8 tile slots per (k,ch) and write centersIterout
    float sum = 0.f;
    #pragma unroll
    for (int i = 0; i < 8; i++) sum += __ldcg(&g_part[t*8 + i]);

    int k = t >> 7;
    float num = (k ? (float)s_cnt : (float)(NPIX - s_cnt)) + 1.0f;
    float mean = sum / num;
    float ci = Cinit[t];
    out[OFF_CENTERS + t] = ci + 0.001f * (mean - ci);

    if (t == 0) g_arrive = 0;       // reset for next graph replay
}

// ---------------------------------------------------------------------------
extern "C" void kernel_launch(void* const* d_in, const int* in_sizes, int n_in,
                              void* d_out, int out_size) {
    const float* F     = (const float*)d_in[0];   // FeatureT [8,128,256,256]
    const float* Cinit = (const float*)d_in[1];   // centerInit [2,128]
    float* out = (float*)d_out;
    (void)in_sizes; (void)n_in; (void)out_size;

    k_b7<<<128, 128>>>(F, Cinit, out);
    k_rest<<<1472, 256>>>(F, Cinit, out);
}

// round 6
// speedup vs baseline: 1.1526x; 1.1526x over previous
#include <cuda_runtime.h>
#include <cstdint>

// Problem constants
#define BB    8
#define C     128
#define W     256
#define H     256
#define NPIX  (W*H)          // 65536 pixels per image
#define NBLK  512            // grid size; all co-resident (one wave)
#define NB7   64             // blocks owning batch 7

// Output buffer layout (concatenated f32, raw reshapes):
#define OFF_CENTERS 0
#define OFF_LABELS  256
#define OFF_ONEHOT  (OFF_LABELS + BB*NPIX)
#define OFF_DIST    (OFF_ONEHOT + BB*2*NPIX)
#define OFF_LABELT  (OFF_DIST   + BB*2*NPIX)

// Scratch (__device__ globals; overwrite-slot semantics, no zero-init needed
// except the two counters which self-reset each run).
// g_mask: batch-7 labels as bits. For float4 index j (0..16383):
//   word = g_mask[j>>5], lane = j&31, label(pixel 4j+c) = bit lane of comp c.
__device__ uint4 g_mask[512];
// g_part[(k*128+ch)*4 + seg]: per-segment per-channel label-k sums (batch 7)
__device__ float g_part[256 * 4];
__device__ int   g_ready  = 0;   // # b7 blocks that published their mask
__device__ int   g_arrive = 0;   // phase-2 arrival counter

// ---------------------------------------------------------------------------
// Single kernel, 512 blocks x 256 threads, guaranteed one wave via
// __launch_bounds__(256,4) (<=64 regs -> 4 blocks/SM -> 592 >= 512 slots).
// Phase 1: per-block main tile (dots, labels, all big outputs; b7 publishes
//          ballot mask and releases g_ready).
// Phase 2: ALL blocks cooperatively re-read F7 (64KB chunk each) for the
//          masked channel sums; deadlock-free spin since all co-resident.
// Epilogue: last-arriving block; counters self-reset for graph replay.
// ---------------------------------------------------------------------------
__global__ void __launch_bounds__(256, 4)
k_all(const float* __restrict__ F,
      const float* __restrict__ Cinit,
      float* __restrict__ out) {
    __shared__ float sc[2*C];
    __shared__ float wa[8], w1[8];
    __shared__ int   wc[8];
    __shared__ int   s_done, s_cnt;

    int t = threadIdx.x;
    sc[t] = Cinit[t];
    __syncthreads();

    int blk  = blockIdx.x;             // 0..511
    int b    = blk >> 6;               // batch 0..7
    int slot = blk & 63;
    int p4   = slot * 256 + t;         // float4-pixel index within image
    int n0   = p4 << 2;
    int wid  = t >> 5, lane = t & 31;
    bool is7 = (b == BB - 1);

    // ---------------- Phase 1: main pass ----------------
    {
        const float4* Fb = reinterpret_cast<const float4*>(F + (size_t)b * C * NPIX);
        float4 a0 = make_float4(0.f,0.f,0.f,0.f);
        float4 a1 = make_float4(0.f,0.f,0.f,0.f);
        if (is7) {
            #pragma unroll 8
            for (int ch = 0; ch < C; ch++) {           // default policy: maybe L2-retained
                float4 f = Fb[ch * (NPIX/4) + p4];
                float c0 = sc[ch], c1 = sc[C + ch];
                a0.x += f.x*c0; a0.y += f.y*c0; a0.z += f.z*c0; a0.w += f.w*c0;
                a1.x += f.x*c1; a1.y += f.y*c1; a1.z += f.z*c1; a1.w += f.w*c1;
            }
        } else {
            #pragma unroll 8
            for (int ch = 0; ch < C; ch++) {           // streaming: evict-first
                float4 f = __ldcs(&Fb[ch * (NPIX/4) + p4]);
                float c0 = sc[ch], c1 = sc[C + ch];
                a0.x += f.x*c0; a0.y += f.y*c0; a0.z += f.z*c0; a0.w += f.w*c0;
                a1.x += f.x*c1; a1.y += f.y*c1; a1.z += f.z*c1; a1.w += f.w*c1;
            }
        }

        float d0x = 0.5f - 0.5f*a0.x, d1x = 0.5f - 0.5f*a1.x;
        float d0y = 0.5f - 0.5f*a0.y, d1y = 0.5f - 0.5f*a1.y;
        float d0z = 0.5f - 0.5f*a0.z, d1z = 0.5f - 0.5f*a1.z;
        float d0w = 0.5f - 0.5f*a0.w, d1w = 0.5f - 0.5f*a1.w;

        int lx = d1x < d0x, ly = d1y < d0y, lz = d1z < d0z, lw = d1w < d0w;
        float4 lab = make_float4((float)lx, (float)ly, (float)lz, (float)lw);

        __stcs(reinterpret_cast<float4*>(out + OFF_LABELS + (size_t)b*NPIX + n0), lab);
        __stcs(reinterpret_cast<float4*>(out + OFF_LABELT + (size_t)b*NPIX + n0), lab);

        float4* outO = reinterpret_cast<float4*>(out + OFF_ONEHOT + (size_t)b*2*NPIX + 2*n0);
        __stcs(outO + 0, make_float4(1.f - lab.x, lab.x, 1.f - lab.y, lab.y));
        __stcs(outO + 1, make_float4(1.f - lab.z, lab.z, 1.f - lab.w, lab.w));

        float4* outD = reinterpret_cast<float4*>(out + OFF_DIST + (size_t)b*2*NPIX + 2*n0);
        __stcs(outD + 0, make_float4(d0x, d1x, d0y, d1y));
        __stcs(outD + 1, make_float4(d0z, d1z, d0w, d1w));

        if (is7) {
            unsigned bx = __ballot_sync(0xffffffffu, lx);
            unsigned by = __ballot_sync(0xffffffffu, ly);
            unsigned bz = __ballot_sync(0xffffffffu, lz);
            unsigned bw = __ballot_sync(0xffffffffu, lw);
            if (lane == 0) g_mask[p4 >> 5] = make_uint4(bx, by, bz, bw);
            __syncthreads();                 // all mask stores of this block issued
            if (t == 0) {
                __threadfence();             // publish mask
                atomicAdd(&g_ready, 1);      // release
            }
        }
    }

    // ---------------- Phase 2: cooperative F7 masked channel sums ----------------
    // Chunk for this block: channel ch = blk & 127, segment seg = blk >> 7.
    // Each thread: 16 float4 (stride 256) => 64KB per block, MLP 16.
    int ch  = blk & 127;
    int seg = blk >> 7;                    // 0..3 (16384 pixels per seg)

    if (t == 0) {                          // wait for full mask (deadlock-free: one wave)
        volatile int* r = &g_ready;
        while (*r < NB7) __nanosleep(128);
    }
    __syncthreads();
    __threadfence();                       // acquire mask

    const float4* Fp = reinterpret_cast<const float4*>(
        F + ((size_t)(BB-1) * C + ch) * NPIX);
    int base = seg * 4096;

    float sa = 0.f, s1 = 0.f;
    #pragma unroll
    for (int i = 0; i < 16; i++) {
        int j = base + i*256 + t;          // j&31 == lane
        float4 f = Fp[j];
        uint4  m = g_mask[j >> 5];
        sa += f.x + f.y + f.z + f.w;
        s1 += f.x*(float)((m.x >> lane) & 1u) + f.y*(float)((m.y >> lane) & 1u)
            + f.z*(float)((m.z >> lane) & 1u) + f.w*(float)((m.w >> lane) & 1u);
    }
    #pragma unroll
    for (int o = 16; o > 0; o >>= 1) {
        sa += __shfl_down_sync(0xffffffffu, sa, o);
        s1 += __shfl_down_sync(0xffffffffu, s1, o);
    }
    if (lane == 0) { wa[wid] = sa; w1[wid] = s1; }
    __syncthreads();
    if (t == 0) {
        float va = 0.f, v1 = 0.f;
        #pragma unroll
        for (int i = 0; i < 8; i++) { va += wa[i]; v1 += w1[i]; }
        g_part[(ch)     * 4 + seg] = va - v1;   // label 0 sum
        g_part[(C + ch) * 4 + seg] = v1;        // label 1 sum
    }

    // ---------------- arrival; last block does the epilogue ----------------
    __syncthreads();
    if (t == 0) {
        __threadfence();
        int old = atomicAdd(&g_arrive, 1);
        s_done = (old == NBLK - 1);
    }
    __syncthreads();
    if (!s_done) return;
    __threadfence();

    // label-1 count via mask popcount (512 uint4 / 256 threads = 2 each)
    {
        uint4 m0 = g_mask[2*t], m1 = g_mask[2*t + 1];
        int c = __popc(m0.x) + __popc(m0.y) + __popc(m0.z) + __popc(m0.w)
              + __popc(m1.x) + __popc(m1.y) + __popc(m1.z) + __popc(m1.w);
        #pragma unroll
        for (int o = 16; o > 0; o >>= 1)
            c += __shfl_down_sync(0xffffffffu, c, o);
        if (lane == 0) wc[wid] = c;
        __syncthreads();
        if (t == 0) {
            int v = 0;
            #pragma unroll
            for (int i = 0; i < 8; i++) v += wc[i];
            s_cnt = v;
        }
        __syncthreads();
    }

    // reduce the 4 seg slots per (k,ch) and write centersIterout
    float sum = 0.f;
    #pragma unroll
    for (int i = 0; i < 4; i++) sum += __ldcg(&g_part[t*4 + i]);

    int k = t >> 7;
    float num = (k ? (float)s_cnt : (float)(NPIX - s_cnt)) + 1.0f;
    float mean = sum / num;
    float ci = sc[t];
    out[OFF_CENTERS + t] = ci + 0.001f * (mean - ci);

    if (t == 0) { g_arrive = 0; g_ready = 0; }   // reset for next graph replay
}

// ---------------------------------------------------------------------------
extern "C" void kernel_launch(void* const* d_in, const int* in_sizes, int n_in,
                              void* d_out, int out_size) {
    const float* F     = (const float*)d_in[0];   // FeatureT [8,128,256,256]
    const float* Cinit = (const float*)d_in[1];   // centerInit [2,128]
    float* out = (float*)d_out;
    (void)in_sizes; (void)n_in; (void)out_size;

    k_all<<<NBLK, 256>>>(F, Cinit, out);
}